// round 11
// baseline (speedup 1.0000x reference)
#include <cuda_runtime.h>
#include <math.h>
#include <stdint.h>

#define NB 32
#define NC 64
#define NH 128
#define NW 128
#define QD 8
#define HWSZ (NH*NW)
#define NEGV (-1e4f)

// ---- device scratch ----
__device__ float g_Q[(size_t)NB*QD*HWSZ];     // [b][q][h][w]
__device__ float g_K[(size_t)NB*QD*HWSZ];     // [b][q][h][w]
__device__ float g_V[(size_t)NB*NC*HWSZ];     // [b][c][h][w]
__device__ float g_MH[(size_t)NB*NC*QD*NW];   // [b][c*8+q][w]
__device__ float g_MW[(size_t)NB*NH*NC*QD];   // [b][h][c*8+q]

__device__ __forceinline__ float softplusf(float v) {
    return fmaxf(v, 0.f) + log1pf(expf(-fabsf(v)));
}

// pack two f32 -> bf16x2 reg: result = {h1 = bf16(hi_src), h0 = bf16(lo_src)}
__device__ __forceinline__ uint32_t packbf(float h1src, float h0src) {
    uint32_t d;
    asm("cvt.rn.bf16x2.f32 %0, %1, %2;" : "=r"(d) : "f"(h1src), "f"(h0src));
    return d;
}
__device__ __forceinline__ float bf_lo(uint32_t p) {   // value of h0
    return __uint_as_float(p << 16);
}
__device__ __forceinline__ float bf_hi(uint32_t p) {   // value of h1
    return __uint_as_float(p & 0xFFFF0000u);
}

// warp-level bf16 mma m16n8k16 (base ISA, sm_80+)
#define MMA_BF16(c, a, bb)                                                    \
    asm volatile("mma.sync.aligned.m16n8k16.row.col.f32.bf16.bf16.f32 "       \
        "{%0,%1,%2,%3}, {%4,%5,%6,%7}, {%8,%9}, {%0,%1,%2,%3};"               \
        : "+f"((c)[0]), "+f"((c)[1]), "+f"((c)[2]), "+f"((c)[3])              \
        : "r"((a)[0]), "r"((a)[1]), "r"((a)[2]), "r"((a)[3]),                 \
          "r"((bb)[0]), "r"((bb)[1]))

// ---- kproj smem layout (u32 words), PT = 128 px = one (b,h) row ----
#define PT    128
#define WSTR  36               // 32 c-pairs + 4 pad
#define XSTR  33               // 32 c-pairs + 1 pad
#define SM_WHI 0                                   // 80*36 = 2880
#define SM_WLO (SM_WHI + 80*WSTR)                  // 2880
#define SM_XHI (SM_WLO + 80*WSTR)                  // 5760
#define SM_XLO (SM_XHI + PT*XSTR)                  // 9984
#define SM_BIA (SM_XLO + PT*XSTR)                  // 14208
#define SM_TOT (SM_BIA + 80)                       // 14288 words = 57152 B
// post-mainloop reuse (overlaps W/X regions, NOT the bias tail):
//   sVf = words [0 .. 64*132)      f32 V row tile
//   sKf = words [64*132 .. 72*132) f32 K row tile (post-softplus)

// ---------------------------------------------------------------
// Kernel A: 1x1 projections via mma.sync bf16 m16n8k16 (3-way split)
// FUSED with the M_W row reduction.
// Block = one (b,h) row of 128 px. 256 thr = 8 warps.
// ---------------------------------------------------------------
__global__ void __launch_bounds__(256, 2) kproj(
    const float* __restrict__ x,
    const float* __restrict__ wq, const float* __restrict__ bq,
    const float* __restrict__ wk, const float* __restrict__ bk,
    const float* __restrict__ wv, const float* __restrict__ bv)
{
    extern __shared__ float smf[];
    uint32_t* sm = reinterpret_cast<uint32_t*>(smf);
    int tid = threadIdx.x;
    int b  = blockIdx.x >> 7;
    int h  = blockIdx.x & 127;
    int p0 = h * PT;

    // ---- stage W hi/lo as bf16x2 c-pairs: sW[o*36 + cp] ----
    for (int i = tid; i < 80*32; i += 256) {
        int o = i >> 5, cp = i & 31;
        const float* wrow = (o < 64) ? (wv + o*64)
                          : (o < 72) ? (wq + (o-64)*64)
                          :            (wk + (o-72)*64);
        float2 wp = *reinterpret_cast<const float2*>(wrow + 2*cp);
        uint32_t hi = packbf(wp.y, wp.x);
        uint32_t lo = packbf(wp.y - bf_hi(hi), wp.x - bf_lo(hi));
        sm[SM_WHI + o*WSTR + cp] = hi;
        sm[SM_WLO + o*WSTR + cp] = lo;
    }
    if (tid < 80)
        smf[SM_BIA + tid] = (tid < 64) ? bv[tid]
                          : (tid < 72) ? bq[tid-64] : bk[tid-72];

    // ---- stage X hi/lo: sX[px*33 + cp] ----
    {
        const float* xb = x + (size_t)b*NC*HWSZ + p0;
        for (int i = tid; i < 32*32; i += 256) {      // 32 cp * 32 px-quads
            int p4 = i & 31, cp = i >> 5;
            const float* x0 = xb + (size_t)(2*cp)*HWSZ + p4*4;
            float4 A4 = *reinterpret_cast<const float4*>(x0);
            float4 B4 = *reinterpret_cast<const float4*>(x0 + HWSZ);
            float av[4] = {A4.x, A4.y, A4.z, A4.w};
            float bv4[4] = {B4.x, B4.y, B4.z, B4.w};
#pragma unroll
            for (int u = 0; u < 4; u++) {
                uint32_t hi = packbf(bv4[u], av[u]);
                uint32_t lo = packbf(bv4[u] - bf_hi(hi), av[u] - bf_lo(hi));
                int px = p4*4 + u;
                sm[SM_XHI + px*XSTR + cp] = hi;
                sm[SM_XLO + px*XSTR + cp] = lo;
            }
        }
    }
    __syncthreads();

    int lane = tid & 31, wid = tid >> 5;
    int lq = lane >> 2;           // 0..7
    int lr = lane & 3;            // 0..3
    int wpx = wid * 16;           // warp pixel base (8 warps x 16 px)

    float acc[5][2][4];
#pragma unroll
    for (int mt = 0; mt < 5; mt++) {
        float b0 = smf[SM_BIA + mt*16 + lq];
        float b1 = smf[SM_BIA + mt*16 + 8 + lq];
#pragma unroll
        for (int j = 0; j < 2; j++) {
            acc[mt][j][0] = b0; acc[mt][j][1] = b0;
            acc[mt][j][2] = b1; acc[mt][j][3] = b1;
        }
    }

#pragma unroll
    for (int ks = 0; ks < 4; ks++) {      // K = 4 x 16
        uint32_t ah[5][4], al[5][4];
#pragma unroll
        for (int mt = 0; mt < 5; mt++) {
            int r0 = (mt*16 + lq)*WSTR + ks*8 + lr;
            int r1 = r0 + 8*WSTR;
            ah[mt][0] = sm[SM_WHI + r0];     ah[mt][1] = sm[SM_WHI + r1];
            ah[mt][2] = sm[SM_WHI + r0 + 4]; ah[mt][3] = sm[SM_WHI + r1 + 4];
            al[mt][0] = sm[SM_WLO + r0];     al[mt][1] = sm[SM_WLO + r1];
            al[mt][2] = sm[SM_WLO + r0 + 4]; al[mt][3] = sm[SM_WLO + r1 + 4];
        }
        uint32_t bh[2][2], bl[2][2];
#pragma unroll
        for (int j = 0; j < 2; j++) {
            int r0 = (wpx + j*8 + lq)*XSTR + ks*8 + lr;
            bh[j][0] = sm[SM_XHI + r0]; bh[j][1] = sm[SM_XHI + r0 + 4];
            bl[j][0] = sm[SM_XLO + r0]; bl[j][1] = sm[SM_XLO + r0 + 4];
        }
#pragma unroll
        for (int mt = 0; mt < 5; mt++)
#pragma unroll
            for (int j = 0; j < 2; j++) MMA_BF16(acc[mt][j], ah[mt], bh[j]);
#pragma unroll
        for (int mt = 0; mt < 5; mt++)
#pragma unroll
            for (int j = 0; j < 2; j++) MMA_BF16(acc[mt][j], ah[mt], bl[j]);
#pragma unroll
        for (int mt = 0; mt < 5; mt++)
#pragma unroll
            for (int j = 0; j < 2; j++) MMA_BF16(acc[mt][j], al[mt], bh[j]);
    }

    // ---- epilogue: store V/Q/K to global AND V,K (f32) to smem ----
    __syncthreads();               // mainloop smem reads done before overwrite
    float* sVf = smf;              // [64][132]
    float* sKf = smf + 64*132;     // [8][132]
    float* Vb = g_V + (size_t)b*NC*HWSZ + p0;
#pragma unroll
    for (int mt = 0; mt < 4; mt++) {
        int r0 = mt*16 + lq, r1 = r0 + 8;
#pragma unroll
        for (int j = 0; j < 2; j++) {
            int px = wpx + j*8 + lr*2;
            float2 v0 = make_float2(acc[mt][j][0], acc[mt][j][1]);
            float2 v1 = make_float2(acc[mt][j][2], acc[mt][j][3]);
            *reinterpret_cast<float2*>(Vb + (size_t)r0*HWSZ + px) = v0;
            *reinterpret_cast<float2*>(Vb + (size_t)r1*HWSZ + px) = v1;
            *reinterpret_cast<float2*>(&sVf[r0*132 + px]) = v0;
            *reinterpret_cast<float2*>(&sVf[r1*132 + px]) = v1;
        }
    }
    {
        float* Qb = g_Q + ((size_t)b*QD + lq)*HWSZ + p0;
        float* Kb = g_K + ((size_t)b*QD + lq)*HWSZ + p0;
#pragma unroll
        for (int j = 0; j < 2; j++) {
            int px = wpx + j*8 + lr*2;
            float2 qv = make_float2(softplusf(acc[4][j][0]),
                                    softplusf(acc[4][j][1]));
            float2 kv = make_float2(softplusf(acc[4][j][2]),
                                    softplusf(acc[4][j][3]));
            *reinterpret_cast<float2*>(Qb + px) = qv;
            *reinterpret_cast<float2*>(Kb + px) = kv;
            *reinterpret_cast<float2*>(&sKf[lq*132 + px]) = kv;
        }
    }
    __syncthreads();

    // ---- fused M_W: M_W[b,h,c,q] = sum_w V[c,w]*K[q,w] ----
    {
        int c = tid >> 2, q0 = (tid & 3) * 2;
        float a0 = 0.f, a1 = 0.f;
#pragma unroll 8
        for (int w4 = 0; w4 < NW/4; w4++) {
            float4 v  = *reinterpret_cast<const float4*>(&sVf[c*132 + w4*4]);
            float4 k0 = *reinterpret_cast<const float4*>(&sKf[q0*132 + w4*4]);
            float4 k1 = *reinterpret_cast<const float4*>(&sKf[(q0+1)*132 + w4*4]);
            a0 = fmaf(v.x, k0.x, a0); a0 = fmaf(v.y, k0.y, a0);
            a0 = fmaf(v.z, k0.z, a0); a0 = fmaf(v.w, k0.w, a0);
            a1 = fmaf(v.x, k1.x, a1); a1 = fmaf(v.y, k1.y, a1);
            a1 = fmaf(v.z, k1.z, a1); a1 = fmaf(v.w, k1.w, a1);
        }
        float2* mwout = reinterpret_cast<float2*>(
            g_MW + ((size_t)b*NH + h)*NC*QD);
        mwout[tid] = make_float2(a0, a1);
    }
}

// ---------------------------------------------------------------
// Kernel C: M_H[b,(c*8+q),w] = sum_h V[b,c,h,w] * K[b,q,h,w]
// ---------------------------------------------------------------
__global__ void __launch_bounds__(1024) kmh()
{
    __shared__ float sV[NC*4*32];
    __shared__ float sK[QD*4*32];
    int tid = threadIdx.x;
    int b = blockIdx.x >> 2;
    int w0 = (blockIdx.x & 3) * 32;
    int w = tid & 31, ch = tid >> 5;

    float acc[16];
#pragma unroll
    for (int i = 0; i < 16; i++) acc[i] = 0.f;

    const float* Vb = g_V + (size_t)b*NC*HWSZ + w0;
    const float* Kb = g_K + (size_t)b*QD*HWSZ + w0;

    for (int h0 = 0; h0 < NH; h0 += 4) {
        __syncthreads();
#pragma unroll
        for (int i = 0; i < 2; i++) {
            int idx4 = tid + i*1024;
            int c = idx4 >> 5, rem = idx4 & 31;
            int hh = rem >> 3, j = rem & 7;
            float4 v = *reinterpret_cast<const float4*>(
                Vb + (size_t)c*HWSZ + (h0 + hh)*NW + j*4);
            *reinterpret_cast<float4*>(&sV[(c*4 + hh)*32 + j*4]) = v;
        }
        if (tid < 256) {
            int q = tid >> 5, rem = tid & 31;
            int hh = rem >> 3, j = rem & 7;
            float4 v = *reinterpret_cast<const float4*>(
                Kb + (size_t)q*HWSZ + (h0 + hh)*NW + j*4);
            *reinterpret_cast<float4*>(&sK[(q*4 + hh)*32 + j*4]) = v;
        }
        __syncthreads();
#pragma unroll
        for (int hh = 0; hh < 4; hh++) {
            float v0 = sV[(ch*4 + hh)*32 + w];
            float v1 = sV[((ch + 32)*4 + hh)*32 + w];
#pragma unroll
            for (int q = 0; q < QD; q++) {
                float kk = sK[(q*4 + hh)*32 + w];
                acc[q]     = fmaf(v0, kk, acc[q]);
                acc[8 + q] = fmaf(v1, kk, acc[8 + q]);
            }
        }
    }
    float* out = g_MH + (size_t)b*NC*QD*NW + w0 + w;
#pragma unroll
    for (int q = 0; q < QD; q++) {
        out[(size_t)(ch*QD + q)*NW]        = acc[q];
        out[(size_t)((ch + 32)*QD + q)*NW] = acc[8 + q];
    }
}

// ---------------------------------------------------------------
// Kernel D: out = gamma*( sum_q Q*(MH+MW) + NEG*V ) + x
// ---------------------------------------------------------------
__global__ void __launch_bounds__(256, 6) kout(
    const float* __restrict__ x,
    const float* __restrict__ gamma,
    float* __restrict__ out)
{
    __shared__ __align__(16) float sMH[16*QD*32];
    __shared__ __align__(16) float sMW[8*16*QD];
    int tid = threadIdx.x;
    int w0 = blockIdx.x * 32, h0 = blockIdx.y * 8;
    int b  = blockIdx.z >> 2;
    int c0 = (blockIdx.z & 3) * 16;
    int lane = tid & 31, hl = tid >> 5;

#pragma unroll
    for (int i = 0; i < 4; i++) {
        int idx4 = tid + i*256;
        int cql = idx4 >> 3, j = idx4 & 7;
        float4 v = *reinterpret_cast<const float4*>(
            g_MH + ((size_t)b*NC*QD + c0*QD + cql)*NW + w0 + j*4);
        *reinterpret_cast<float4*>(&sMH[cql*32 + j*4]) = v;
    }
    {
        int hh = tid >> 5, j = tid & 31;
        float4 v = *reinterpret_cast<const float4*>(
            g_MW + ((size_t)(b*NH + h0 + hh)*NC + c0)*QD + j*4);
        *reinterpret_cast<float4*>(&sMW[hh*(16*QD) + j*4]) = v;
    }

    int h = h0 + hl, w = w0 + lane;
    float Qr[QD];
#pragma unroll
    for (int q = 0; q < QD; q++)
        Qr[q] = g_Q[((size_t)b*QD + q)*HWSZ + h*NW + w];
    float gm = gamma[0];
    __syncthreads();

    const float* Vp = g_V + ((size_t)b*NC + c0)*HWSZ + h*NW + w;
    const float* Xp = x   + ((size_t)b*NC + c0)*HWSZ + h*NW + w;
    float*       Op = out + ((size_t)b*NC + c0)*HWSZ + h*NW + w;

#pragma unroll
    for (int cc = 0; cc < 16; cc += 4) {
        float v[4], xr[4];
#pragma unroll
        for (int u = 0; u < 4; u++) {
            v[u]  = Vp[(size_t)(cc+u)*HWSZ];
            xr[u] = Xp[(size_t)(cc+u)*HWSZ];
        }
#pragma unroll
        for (int u = 0; u < 4; u++) {
            int c = cc + u;
            const float* mh = &sMH[c*QD*32 + lane];
            const float4* mwp = reinterpret_cast<const float4*>(&sMW[hl*(16*QD) + c*QD]);
            float4 a = mwp[0], bb = mwp[1];
            float acc;
            acc  = (mh[0]   + a.x)  * Qr[0];
            acc += (mh[32]  + a.y)  * Qr[1];
            acc += (mh[64]  + a.z)  * Qr[2];
            acc += (mh[96]  + a.w)  * Qr[3];
            acc += (mh[128] + bb.x) * Qr[4];
            acc += (mh[160] + bb.y) * Qr[5];
            acc += (mh[192] + bb.z) * Qr[6];
            acc += (mh[224] + bb.w) * Qr[7];
            Op[(size_t)c*HWSZ] = fmaf(gm, fmaf(NEGV, v[u], acc), xr[u]);
        }
    }
}

// ---------------------------------------------------------------
extern "C" void kernel_launch(void* const* d_in, const int* in_sizes, int n_in,
                              void* d_out, int out_size)
{
    const float* x     = (const float*)d_in[0];
    const float* wq    = (const float*)d_in[1];
    const float* bq    = (const float*)d_in[2];
    const float* wk    = (const float*)d_in[3];
    const float* bk    = (const float*)d_in[4];
    const float* wv    = (const float*)d_in[5];
    const float* bv    = (const float*)d_in[6];
    const float* gamma = (const float*)d_in[7];
    float* out = (float*)d_out;

    const int smproj = SM_TOT * sizeof(float);   // ~57 KB
    cudaFuncSetAttribute(kproj, cudaFuncAttributeMaxDynamicSharedMemorySize,
                         smproj);

    kproj<<<NB*NH, 256, smproj>>>(x, wq, bq, wk, bk, wv, bv);
    kmh<<<NB*4, 1024>>>();
    kout<<<dim3(NW/32, NH/8, NB*4), 256>>>(x, gamma, out);
}

// round 12
// speedup vs baseline: 1.0163x; 1.0163x over previous
#include <cuda_runtime.h>
#include <math.h>
#include <stdint.h>

#define NB 32
#define NC 64
#define NH 128
#define NW 128
#define QD 8
#define HWSZ (NH*NW)
#define NEGV (-1e4f)

// ---- device scratch ----
__device__ float g_Q[(size_t)NB*QD*HWSZ];     // [b][q][h][w]
__device__ float g_K[(size_t)NB*QD*HWSZ];     // [b][q][h][w]
__device__ float g_V[(size_t)NB*NC*HWSZ];     // [b][c][h][w]
__device__ float g_MH[(size_t)NB*NC*QD*NW];   // [b][c*8+q][w]
__device__ float g_MW[(size_t)NB*NH*NC*QD];   // [b][h][c*8+q]

__device__ __forceinline__ float softplusf(float v) {
    return fmaxf(v, 0.f) + log1pf(expf(-fabsf(v)));
}

// pack two f32 -> bf16x2 reg: result = {h1 = bf16(hi_src), h0 = bf16(lo_src)}
__device__ __forceinline__ uint32_t packbf(float h1src, float h0src) {
    uint32_t d;
    asm("cvt.rn.bf16x2.f32 %0, %1, %2;" : "=r"(d) : "f"(h1src), "f"(h0src));
    return d;
}
__device__ __forceinline__ float bf_lo(uint32_t p) {   // value of h0
    return __uint_as_float(p << 16);
}
__device__ __forceinline__ float bf_hi(uint32_t p) {   // value of h1
    return __uint_as_float(p & 0xFFFF0000u);
}

// warp-level bf16 mma m16n8k16 (base ISA, sm_80+)
#define MMA_BF16(c, a, bb)                                                    \
    asm volatile("mma.sync.aligned.m16n8k16.row.col.f32.bf16.bf16.f32 "       \
        "{%0,%1,%2,%3}, {%4,%5,%6,%7}, {%8,%9}, {%0,%1,%2,%3};"               \
        : "+f"((c)[0]), "+f"((c)[1]), "+f"((c)[2]), "+f"((c)[3])              \
        : "r"((a)[0]), "r"((a)[1]), "r"((a)[2]), "r"((a)[3]),                 \
          "r"((bb)[0]), "r"((bb)[1]))

// ---- kproj smem layout (u32 words), PT = 128 px = one (b,h) row ----
#define PT    128
#define WSTR  36               // W: [o][36]  (bank = 4*lq+lr, distinct)
#define XP    136              // X: [cp][136] (bank = 8*lr+lq, distinct)
#define SM_WHI 0                                   // 80*36 = 2880
#define SM_WLO (SM_WHI + 80*WSTR)                  // 2880
#define SM_XHI (SM_WLO + 80*WSTR)                  // 5760
#define SM_XLO (SM_XHI + 32*XP)                    // 10112
#define SM_BIA (SM_XLO + 32*XP)                    // 14464
#define SM_TOT (SM_BIA + 80)                       // 14544 words = 58176 B
// post-mainloop reuse (overlaps W/X regions, NOT the bias tail):
//   sVf = words [0 .. 64*132)      f32 V row tile
//   sKf = words [64*132 .. 72*132) f32 K row tile  (9504 < 14464, safe)

// ---------------------------------------------------------------
// Kernel A: 1x1 projections via mma.sync bf16 m16n8k16 (3-way split)
// FUSED with the M_W row reduction. Block = one (b,h) row, 8 warps.
// ---------------------------------------------------------------
__global__ void __launch_bounds__(256, 2) kproj(
    const float* __restrict__ x,
    const float* __restrict__ wq, const float* __restrict__ bq,
    const float* __restrict__ wk, const float* __restrict__ bk,
    const float* __restrict__ wv, const float* __restrict__ bv)
{
    extern __shared__ float smf[];
    uint32_t* sm = reinterpret_cast<uint32_t*>(smf);
    int tid = threadIdx.x;
    int b  = blockIdx.x >> 7;
    int h  = blockIdx.x & 127;
    int p0 = h * PT;

    // ---- stage W hi/lo as bf16x2 c-pairs: sW[o*36 + cp] ----
    for (int i = tid; i < 80*32; i += 256) {
        int o = i >> 5, cp = i & 31;
        const float* wrow = (o < 64) ? (wv + o*64)
                          : (o < 72) ? (wq + (o-64)*64)
                          :            (wk + (o-72)*64);
        float2 wp = *reinterpret_cast<const float2*>(wrow + 2*cp);
        uint32_t hi = packbf(wp.y, wp.x);
        uint32_t lo = packbf(wp.y - bf_hi(hi), wp.x - bf_lo(hi));
        sm[SM_WHI + o*WSTR + cp] = hi;
        sm[SM_WLO + o*WSTR + cp] = lo;
    }
    if (tid < 80)
        smf[SM_BIA + tid] = (tid < 64) ? bv[tid]
                          : (tid < 72) ? bq[tid-64] : bk[tid-72];

    // ---- stage X hi/lo: sX[cp*136 + px]; warp = one cp row ----
    {
        const float* xb = x + (size_t)b*NC*HWSZ + p0;
        for (int i = tid; i < 32*32; i += 256) {      // 32 cp * 32 px-quads
            int cp = i >> 5, p4 = i & 31;
            const float* x0 = xb + (size_t)(2*cp)*HWSZ + p4*4;
            float4 A4 = *reinterpret_cast<const float4*>(x0);         // c=2cp
            float4 B4 = *reinterpret_cast<const float4*>(x0 + HWSZ);  // c=2cp+1
            float av[4] = {A4.x, A4.y, A4.z, A4.w};
            float bv4[4] = {B4.x, B4.y, B4.z, B4.w};
            uint32_t hi[4], lo[4];
#pragma unroll
            for (int u = 0; u < 4; u++) {
                hi[u] = packbf(bv4[u], av[u]);
                lo[u] = packbf(bv4[u] - bf_hi(hi[u]), av[u] - bf_lo(hi[u]));
            }
            *reinterpret_cast<uint4*>(&sm[SM_XHI + cp*XP + p4*4]) =
                make_uint4(hi[0], hi[1], hi[2], hi[3]);
            *reinterpret_cast<uint4*>(&sm[SM_XLO + cp*XP + p4*4]) =
                make_uint4(lo[0], lo[1], lo[2], lo[3]);
        }
    }
    __syncthreads();

    int lane = tid & 31, wid = tid >> 5;
    int lq = lane >> 2;           // 0..7
    int lr = lane & 3;            // 0..3
    int wpx = wid * 16;           // warp pixel base (8 warps x 16 px)

    float acc[5][2][4];
#pragma unroll
    for (int mt = 0; mt < 5; mt++) {
        float b0 = smf[SM_BIA + mt*16 + lq];
        float b1 = smf[SM_BIA + mt*16 + 8 + lq];
#pragma unroll
        for (int j = 0; j < 2; j++) {
            acc[mt][j][0] = b0; acc[mt][j][1] = b0;
            acc[mt][j][2] = b1; acc[mt][j][3] = b1;
        }
    }

#pragma unroll
    for (int ks = 0; ks < 4; ks++) {      // K = 4 x 16
        uint32_t ah[5][4], al[5][4];
#pragma unroll
        for (int mt = 0; mt < 5; mt++) {
            int r0 = (mt*16 + lq)*WSTR + ks*8 + lr;
            int r1 = r0 + 8*WSTR;
            ah[mt][0] = sm[SM_WHI + r0];     ah[mt][1] = sm[SM_WHI + r1];
            ah[mt][2] = sm[SM_WHI + r0 + 4]; ah[mt][3] = sm[SM_WHI + r1 + 4];
            al[mt][0] = sm[SM_WLO + r0];     al[mt][1] = sm[SM_WLO + r1];
            al[mt][2] = sm[SM_WLO + r0 + 4]; al[mt][3] = sm[SM_WLO + r1 + 4];
        }
        uint32_t bh[2][2], bl[2][2];
#pragma unroll
        for (int j = 0; j < 2; j++) {
            int r0 = (ks*8 + lr)*XP + wpx + j*8 + lq;   // b0: k-pair = lr
            bh[j][0] = sm[SM_XHI + r0]; bh[j][1] = sm[SM_XHI + r0 + 4*XP];
            bl[j][0] = sm[SM_XLO + r0]; bl[j][1] = sm[SM_XLO + r0 + 4*XP];
        }
#pragma unroll
        for (int mt = 0; mt < 5; mt++)
#pragma unroll
            for (int j = 0; j < 2; j++) MMA_BF16(acc[mt][j], ah[mt], bh[j]);
#pragma unroll
        for (int mt = 0; mt < 5; mt++)
#pragma unroll
            for (int j = 0; j < 2; j++) MMA_BF16(acc[mt][j], ah[mt], bl[j]);
#pragma unroll
        for (int mt = 0; mt < 5; mt++)
#pragma unroll
            for (int j = 0; j < 2; j++) MMA_BF16(acc[mt][j], al[mt], bh[j]);
    }

    // ---- epilogue: store V/Q/K to global AND V,K (f32) to smem ----
    __syncthreads();               // mainloop smem reads done before overwrite
    float* sVf = smf;              // [64][132]
    float* sKf = smf + 64*132;     // [8][132]
    float* Vb = g_V + (size_t)b*NC*HWSZ + p0;
#pragma unroll
    for (int mt = 0; mt < 4; mt++) {
        int r0 = mt*16 + lq, r1 = r0 + 8;
#pragma unroll
        for (int j = 0; j < 2; j++) {
            int px = wpx + j*8 + lr*2;
            float2 v0 = make_float2(acc[mt][j][0], acc[mt][j][1]);
            float2 v1 = make_float2(acc[mt][j][2], acc[mt][j][3]);
            *reinterpret_cast<float2*>(Vb + (size_t)r0*HWSZ + px) = v0;
            *reinterpret_cast<float2*>(Vb + (size_t)r1*HWSZ + px) = v1;
            *reinterpret_cast<float2*>(&sVf[r0*132 + px]) = v0;
            *reinterpret_cast<float2*>(&sVf[r1*132 + px]) = v1;
        }
    }
    {
        float* Qb = g_Q + ((size_t)b*QD + lq)*HWSZ + p0;
        float* Kb = g_K + ((size_t)b*QD + lq)*HWSZ + p0;
#pragma unroll
        for (int j = 0; j < 2; j++) {
            int px = wpx + j*8 + lr*2;
            float2 qv = make_float2(softplusf(acc[4][j][0]),
                                    softplusf(acc[4][j][1]));
            float2 kv = make_float2(softplusf(acc[4][j][2]),
                                    softplusf(acc[4][j][3]));
            *reinterpret_cast<float2*>(Qb + px) = qv;
            *reinterpret_cast<float2*>(Kb + px) = kv;
            *reinterpret_cast<float2*>(&sKf[lq*132 + px]) = kv;
        }
    }
    __syncthreads();

    // ---- fused M_W: M_W[b,h,c,q] = sum_w V[c,w]*K[q,w] ----
    {
        int c = tid >> 2, q0 = (tid & 3) * 2;
        float a0 = 0.f, a1 = 0.f;
#pragma unroll 8
        for (int w4 = 0; w4 < NW/4; w4++) {
            float4 v  = *reinterpret_cast<const float4*>(&sVf[c*132 + w4*4]);
            float4 k0 = *reinterpret_cast<const float4*>(&sKf[q0*132 + w4*4]);
            float4 k1 = *reinterpret_cast<const float4*>(&sKf[(q0+1)*132 + w4*4]);
            a0 = fmaf(v.x, k0.x, a0); a0 = fmaf(v.y, k0.y, a0);
            a0 = fmaf(v.z, k0.z, a0); a0 = fmaf(v.w, k0.w, a0);
            a1 = fmaf(v.x, k1.x, a1); a1 = fmaf(v.y, k1.y, a1);
            a1 = fmaf(v.z, k1.z, a1); a1 = fmaf(v.w, k1.w, a1);
        }
        float2* mwout = reinterpret_cast<float2*>(
            g_MW + ((size_t)b*NH + h)*NC*QD);
        mwout[tid] = make_float2(a0, a1);
    }
}

// ---------------------------------------------------------------
// Kernel C: M_H[b,(c*8+q),w] = sum_h V[b,c,h,w] * K[b,q,h,w]
// ---------------------------------------------------------------
__global__ void __launch_bounds__(1024) kmh()
{
    __shared__ float sV[NC*4*32];
    __shared__ float sK[QD*4*32];
    int tid = threadIdx.x;
    int b = blockIdx.x >> 2;
    int w0 = (blockIdx.x & 3) * 32;
    int w = tid & 31, ch = tid >> 5;

    float acc[16];
#pragma unroll
    for (int i = 0; i < 16; i++) acc[i] = 0.f;

    const float* Vb = g_V + (size_t)b*NC*HWSZ + w0;
    const float* Kb = g_K + (size_t)b*QD*HWSZ + w0;

    for (int h0 = 0; h0 < NH; h0 += 4) {
        __syncthreads();
#pragma unroll
        for (int i = 0; i < 2; i++) {
            int idx4 = tid + i*1024;
            int c = idx4 >> 5, rem = idx4 & 31;
            int hh = rem >> 3, j = rem & 7;
            float4 v = *reinterpret_cast<const float4*>(
                Vb + (size_t)c*HWSZ + (h0 + hh)*NW + j*4);
            *reinterpret_cast<float4*>(&sV[(c*4 + hh)*32 + j*4]) = v;
        }
        if (tid < 256) {
            int q = tid >> 5, rem = tid & 31;
            int hh = rem >> 3, j = rem & 7;
            float4 v = *reinterpret_cast<const float4*>(
                Kb + (size_t)q*HWSZ + (h0 + hh)*NW + j*4);
            *reinterpret_cast<float4*>(&sK[(q*4 + hh)*32 + j*4]) = v;
        }
        __syncthreads();
#pragma unroll
        for (int hh = 0; hh < 4; hh++) {
            float v0 = sV[(ch*4 + hh)*32 + w];
            float v1 = sV[((ch + 32)*4 + hh)*32 + w];
#pragma unroll
            for (int q = 0; q < QD; q++) {
                float kk = sK[(q*4 + hh)*32 + w];
                acc[q]     = fmaf(v0, kk, acc[q]);
                acc[8 + q] = fmaf(v1, kk, acc[8 + q]);
            }
        }
    }
    float* out = g_MH + (size_t)b*NC*QD*NW + w0 + w;
#pragma unroll
    for (int q = 0; q < QD; q++) {
        out[(size_t)(ch*QD + q)*NW]        = acc[q];
        out[(size_t)((ch + 32)*QD + q)*NW] = acc[8 + q];
    }
}

// ---------------------------------------------------------------
// Kernel D: out = gamma*( sum_q Q*(MH+MW) + NEG*V ) + x
// ---------------------------------------------------------------
__global__ void __launch_bounds__(256, 6) kout(
    const float* __restrict__ x,
    const float* __restrict__ gamma,
    float* __restrict__ out)
{
    __shared__ __align__(16) float sMH[16*QD*32];
    __shared__ __align__(16) float sMW[8*16*QD];
    int tid = threadIdx.x;
    int w0 = blockIdx.x * 32, h0 = blockIdx.y * 8;
    int b  = blockIdx.z >> 2;
    int c0 = (blockIdx.z & 3) * 16;
    int lane = tid & 31, hl = tid >> 5;

#pragma unroll
    for (int i = 0; i < 4; i++) {
        int idx4 = tid + i*256;
        int cql = idx4 >> 3, j = idx4 & 7;
        float4 v = *reinterpret_cast<const float4*>(
            g_MH + ((size_t)b*NC*QD + c0*QD + cql)*NW + w0 + j*4);
        *reinterpret_cast<float4*>(&sMH[cql*32 + j*4]) = v;
    }
    {
        int hh = tid >> 5, j = tid & 31;
        float4 v = *reinterpret_cast<const float4*>(
            g_MW + ((size_t)(b*NH + h0 + hh)*NC + c0)*QD + j*4);
        *reinterpret_cast<float4*>(&sMW[hh*(16*QD) + j*4]) = v;
    }

    int h = h0 + hl, w = w0 + lane;
    float Qr[QD];
#pragma unroll
    for (int q = 0; q < QD; q++)
        Qr[q] = g_Q[((size_t)b*QD + q)*HWSZ + h*NW + w];
    float gm = gamma[0];
    __syncthreads();

    const float* Vp = g_V + ((size_t)b*NC + c0)*HWSZ + h*NW + w;
    const float* Xp = x   + ((size_t)b*NC + c0)*HWSZ + h*NW + w;
    float*       Op = out + ((size_t)b*NC + c0)*HWSZ + h*NW + w;

#pragma unroll
    for (int cc = 0; cc < 16; cc += 4) {
        float v[4], xr[4];
#pragma unroll
        for (int u = 0; u < 4; u++) {
            v[u]  = Vp[(size_t)(cc+u)*HWSZ];
            xr[u] = Xp[(size_t)(cc+u)*HWSZ];
        }
#pragma unroll
        for (int u = 0; u < 4; u++) {
            int c = cc + u;
            const float* mh = &sMH[c*QD*32 + lane];
            const float4* mwp = reinterpret_cast<const float4*>(&sMW[hl*(16*QD) + c*QD]);
            float4 a = mwp[0], bb = mwp[1];
            float acc;
            acc  = (mh[0]   + a.x)  * Qr[0];
            acc += (mh[32]  + a.y)  * Qr[1];
            acc += (mh[64]  + a.z)  * Qr[2];
            acc += (mh[96]  + a.w)  * Qr[3];
            acc += (mh[128] + bb.x) * Qr[4];
            acc += (mh[160] + bb.y) * Qr[5];
            acc += (mh[192] + bb.z) * Qr[6];
            acc += (mh[224] + bb.w) * Qr[7];
            Op[(size_t)c*HWSZ] = fmaf(gm, fmaf(NEGV, v[u], acc), xr[u]);
        }
    }
}

// ---------------------------------------------------------------
extern "C" void kernel_launch(void* const* d_in, const int* in_sizes, int n_in,
                              void* d_out, int out_size)
{
    const float* x     = (const float*)d_in[0];
    const float* wq    = (const float*)d_in[1];
    const float* bq    = (const float*)d_in[2];
    const float* wk    = (const float*)d_in[3];
    const float* bk    = (const float*)d_in[4];
    const float* wv    = (const float*)d_in[5];
    const float* bv    = (const float*)d_in[6];
    const float* gamma = (const float*)d_in[7];
    float* out = (float*)d_out;

    const int smproj = SM_TOT * sizeof(float);   // ~58 KB
    cudaFuncSetAttribute(kproj, cudaFuncAttributeMaxDynamicSharedMemorySize,
                         smproj);

    kproj<<<NB*NH, 256, smproj>>>(x, wq, bq, wk, bk, wv, bv);
    kmh<<<NB*4, 1024>>>();
    kout<<<dim3(NW/32, NH/8, NB*4), 256>>>(x, gamma, out);
}

// round 13
// speedup vs baseline: 1.1416x; 1.1234x over previous
#include <cuda_runtime.h>
#include <math.h>
#include <stdint.h>

#define NB 32
#define NC 64
#define NH 128
#define NW 128
#define QD 8
#define HWSZ (NH*NW)
#define NEGV (-1e4f)

// ---- device scratch ----
__device__ float g_Q[(size_t)NB*QD*HWSZ];     // [b][q][h][w]
__device__ float g_K[(size_t)NB*QD*HWSZ];     // [b][q][h][w]
__device__ float g_V[(size_t)NB*NC*HWSZ];     // [b][c][h][w]
__device__ float g_MH[(size_t)NB*NC*QD*NW];   // [b][c*8+q][w]
__device__ float g_MW[(size_t)NB*NH*NC*QD];   // [b][h][c*8+q]
__device__ uint32_t g_Whi[80*32];             // pre-split W hi (bf16x2 pairs)
__device__ uint32_t g_Wlo[80*32];             // pre-split W lo
__device__ float    g_Bia[80];                // fused bias

__device__ __forceinline__ float softplusf(float v) {
    return fmaxf(v, 0.f) + log1pf(expf(-fabsf(v)));
}

// pack two f32 -> bf16x2 reg: result = {h1 = bf16(hi_src), h0 = bf16(lo_src)}
__device__ __forceinline__ uint32_t packbf(float h1src, float h0src) {
    uint32_t d;
    asm("cvt.rn.bf16x2.f32 %0, %1, %2;" : "=r"(d) : "f"(h1src), "f"(h0src));
    return d;
}
__device__ __forceinline__ float bf_lo(uint32_t p) {   // value of h0
    return __uint_as_float(p << 16);
}
__device__ __forceinline__ float bf_hi(uint32_t p) {   // value of h1
    return __uint_as_float(p & 0xFFFF0000u);
}

// warp-level bf16 mma m16n8k16 (base ISA, sm_80+)
#define MMA_BF16(c, a, bb)                                                    \
    asm volatile("mma.sync.aligned.m16n8k16.row.col.f32.bf16.bf16.f32 "       \
        "{%0,%1,%2,%3}, {%4,%5,%6,%7}, {%8,%9}, {%0,%1,%2,%3};"               \
        : "+f"((c)[0]), "+f"((c)[1]), "+f"((c)[2]), "+f"((c)[3])              \
        : "r"((a)[0]), "r"((a)[1]), "r"((a)[2]), "r"((a)[3]),                 \
          "r"((bb)[0]), "r"((bb)[1]))

// ---- kproj smem layout (u32 words), PT = 128 px = one (b,h) row ----
#define PT    128
#define WSTR  36               // W: [o][36]  (bank = 4*lq+lr, distinct)
#define XP    136              // X: [cp][136] (bank = 8*lr+lq, distinct)
#define SM_WHI 0                                   // 80*36 = 2880
#define SM_WLO (SM_WHI + 80*WSTR)                  // 2880
#define SM_XHI (SM_WLO + 80*WSTR)                  // 5760
#define SM_XLO (SM_XHI + 32*XP)                    // 10112
#define SM_BIA (SM_XLO + 32*XP)                    // 14464
#define SM_TOT (SM_BIA + 80)                       // 14544 words = 58176 B
// post-mainloop reuse: sVf = [0..64*132), sKf = [64*132..72*132)

// ---------------------------------------------------------------
// Kernel W: one-time weight split (hi/lo bf16x2) + bias gather.
// ---------------------------------------------------------------
__global__ void wsplit(
    const float* __restrict__ wq, const float* __restrict__ bq,
    const float* __restrict__ wk, const float* __restrict__ bk,
    const float* __restrict__ wv, const float* __restrict__ bv)
{
    int i = blockIdx.x * 256 + threadIdx.x;
    if (i < 80*32) {
        int o = i >> 5, cp = i & 31;
        const float* wrow = (o < 64) ? (wv + o*64)
                          : (o < 72) ? (wq + (o-64)*64)
                          :            (wk + (o-72)*64);
        float2 wp = *reinterpret_cast<const float2*>(wrow + 2*cp);
        uint32_t hi = packbf(wp.y, wp.x);
        uint32_t lo = packbf(wp.y - bf_hi(hi), wp.x - bf_lo(hi));
        g_Whi[i] = hi;
        g_Wlo[i] = lo;
    }
    if (i < 80)
        g_Bia[i] = (i < 64) ? bv[i] : (i < 72) ? bq[i-64] : bk[i-72];
}

// ---------------------------------------------------------------
// Kernel A: 1x1 projections via mma.sync bf16 m16n8k16 (3-way split)
// FUSED with the M_W row reduction. Block = one (b,h) row, 8 warps.
// al-fragments loaded late (between pass 2 and 3) to cut reg pressure
// -> 3 CTAs/SM.
// ---------------------------------------------------------------
__global__ void __launch_bounds__(256, 3) kproj(const float* __restrict__ x)
{
    extern __shared__ float smf[];
    uint32_t* sm = reinterpret_cast<uint32_t*>(smf);
    int tid = threadIdx.x;
    int b  = blockIdx.x >> 7;
    int h  = blockIdx.x & 127;
    int p0 = h * PT;

    // ---- stage X hi/lo FIRST (DRAM latency starts now) ----
    {
        const float* xb = x + (size_t)b*NC*HWSZ + p0;
        for (int i = tid; i < 32*32; i += 256) {      // 32 cp * 32 px-quads
            int cp = i >> 5, p4 = i & 31;
            const float* x0 = xb + (size_t)(2*cp)*HWSZ + p4*4;
            float4 A4 = *reinterpret_cast<const float4*>(x0);         // c=2cp
            float4 B4 = *reinterpret_cast<const float4*>(x0 + HWSZ);  // c=2cp+1
            float av[4] = {A4.x, A4.y, A4.z, A4.w};
            float bv4[4] = {B4.x, B4.y, B4.z, B4.w};
            uint32_t hi[4], lo[4];
#pragma unroll
            for (int u = 0; u < 4; u++) {
                hi[u] = packbf(bv4[u], av[u]);
                lo[u] = packbf(bv4[u] - bf_hi(hi[u]), av[u] - bf_lo(hi[u]));
            }
            *reinterpret_cast<uint4*>(&sm[SM_XHI + cp*XP + p4*4]) =
                make_uint4(hi[0], hi[1], hi[2], hi[3]);
            *reinterpret_cast<uint4*>(&sm[SM_XLO + cp*XP + p4*4]) =
                make_uint4(lo[0], lo[1], lo[2], lo[3]);
        }
    }
    // ---- W: plain copy of the pre-split weights (L2-hot) ----
    for (int i = tid; i < 80*32; i += 256) {
        int o = i >> 5, cp = i & 31;
        sm[SM_WHI + o*WSTR + cp] = g_Whi[i];
        sm[SM_WLO + o*WSTR + cp] = g_Wlo[i];
    }
    if (tid < 80) smf[SM_BIA + tid] = g_Bia[tid];
    __syncthreads();

    int lane = tid & 31, wid = tid >> 5;
    int lq = lane >> 2;           // 0..7
    int lr = lane & 3;            // 0..3
    int wpx = wid * 16;           // warp pixel base (8 warps x 16 px)

    float acc[5][2][4];
#pragma unroll
    for (int mt = 0; mt < 5; mt++) {
        float b0 = smf[SM_BIA + mt*16 + lq];
        float b1 = smf[SM_BIA + mt*16 + 8 + lq];
#pragma unroll
        for (int j = 0; j < 2; j++) {
            acc[mt][j][0] = b0; acc[mt][j][1] = b0;
            acc[mt][j][2] = b1; acc[mt][j][3] = b1;
        }
    }

#pragma unroll
    for (int ks = 0; ks < 4; ks++) {      // K = 4 x 16
        uint32_t bh[2][2], bl[2][2];
#pragma unroll
        for (int j = 0; j < 2; j++) {
            int r0 = (ks*8 + lr)*XP + wpx + j*8 + lq;
            bh[j][0] = sm[SM_XHI + r0]; bh[j][1] = sm[SM_XHI + r0 + 4*XP];
            bl[j][0] = sm[SM_XLO + r0]; bl[j][1] = sm[SM_XLO + r0 + 4*XP];
        }
        uint32_t ah[5][4];
#pragma unroll
        for (int mt = 0; mt < 5; mt++) {
            int r0 = (mt*16 + lq)*WSTR + ks*8 + lr;
            int r1 = r0 + 8*WSTR;
            ah[mt][0] = sm[SM_WHI + r0];     ah[mt][1] = sm[SM_WHI + r1];
            ah[mt][2] = sm[SM_WHI + r0 + 4]; ah[mt][3] = sm[SM_WHI + r1 + 4];
        }
#pragma unroll
        for (int mt = 0; mt < 5; mt++)
#pragma unroll
            for (int j = 0; j < 2; j++) MMA_BF16(acc[mt][j], ah[mt], bh[j]);
#pragma unroll
        for (int mt = 0; mt < 5; mt++)
#pragma unroll
            for (int j = 0; j < 2; j++) MMA_BF16(acc[mt][j], ah[mt], bl[j]);
        // load al LATE so it is not co-live with ah across passes 1-2
        uint32_t al[5][4];
#pragma unroll
        for (int mt = 0; mt < 5; mt++) {
            int r0 = (mt*16 + lq)*WSTR + ks*8 + lr;
            int r1 = r0 + 8*WSTR;
            al[mt][0] = sm[SM_WLO + r0];     al[mt][1] = sm[SM_WLO + r1];
            al[mt][2] = sm[SM_WLO + r0 + 4]; al[mt][3] = sm[SM_WLO + r1 + 4];
        }
#pragma unroll
        for (int mt = 0; mt < 5; mt++)
#pragma unroll
            for (int j = 0; j < 2; j++) MMA_BF16(acc[mt][j], al[mt], bh[j]);
    }

    // ---- epilogue: store V/Q/K to global AND V,K (f32) to smem ----
    __syncthreads();               // mainloop smem reads done before overwrite
    float* sVf = smf;              // [64][132]
    float* sKf = smf + 64*132;     // [8][132]
    float* Vb = g_V + (size_t)b*NC*HWSZ + p0;
#pragma unroll
    for (int mt = 0; mt < 4; mt++) {
        int r0 = mt*16 + lq, r1 = r0 + 8;
#pragma unroll
        for (int j = 0; j < 2; j++) {
            int px = wpx + j*8 + lr*2;
            float2 v0 = make_float2(acc[mt][j][0], acc[mt][j][1]);
            float2 v1 = make_float2(acc[mt][j][2], acc[mt][j][3]);
            *reinterpret_cast<float2*>(Vb + (size_t)r0*HWSZ + px) = v0;
            *reinterpret_cast<float2*>(Vb + (size_t)r1*HWSZ + px) = v1;
            *reinterpret_cast<float2*>(&sVf[r0*132 + px]) = v0;
            *reinterpret_cast<float2*>(&sVf[r1*132 + px]) = v1;
        }
    }
    {
        float* Qb = g_Q + ((size_t)b*QD + lq)*HWSZ + p0;
        float* Kb = g_K + ((size_t)b*QD + lq)*HWSZ + p0;
#pragma unroll
        for (int j = 0; j < 2; j++) {
            int px = wpx + j*8 + lr*2;
            float2 qv = make_float2(softplusf(acc[4][j][0]),
                                    softplusf(acc[4][j][1]));
            float2 kv = make_float2(softplusf(acc[4][j][2]),
                                    softplusf(acc[4][j][3]));
            *reinterpret_cast<float2*>(Qb + px) = qv;
            *reinterpret_cast<float2*>(Kb + px) = kv;
            *reinterpret_cast<float2*>(&sKf[lq*132 + px]) = kv;
        }
    }
    __syncthreads();

    // ---- fused M_W: M_W[b,h,c,q] = sum_w V[c,w]*K[q,w] ----
    {
        int c = tid >> 2, q0 = (tid & 3) * 2;
        float a0 = 0.f, a1 = 0.f;
#pragma unroll 8
        for (int w4 = 0; w4 < NW/4; w4++) {
            float4 v  = *reinterpret_cast<const float4*>(&sVf[c*132 + w4*4]);
            float4 k0 = *reinterpret_cast<const float4*>(&sKf[q0*132 + w4*4]);
            float4 k1 = *reinterpret_cast<const float4*>(&sKf[(q0+1)*132 + w4*4]);
            a0 = fmaf(v.x, k0.x, a0); a0 = fmaf(v.y, k0.y, a0);
            a0 = fmaf(v.z, k0.z, a0); a0 = fmaf(v.w, k0.w, a0);
            a1 = fmaf(v.x, k1.x, a1); a1 = fmaf(v.y, k1.y, a1);
            a1 = fmaf(v.z, k1.z, a1); a1 = fmaf(v.w, k1.w, a1);
        }
        float2* mwout = reinterpret_cast<float2*>(
            g_MW + ((size_t)b*NH + h)*NC*QD);
        mwout[tid] = make_float2(a0, a1);
    }
}

// ---------------------------------------------------------------
// Kernel C: M_H[b,(c*8+q),w] = sum_h V[b,c,h,w] * K[b,q,h,w]
// ---------------------------------------------------------------
__global__ void __launch_bounds__(1024) kmh()
{
    __shared__ float sV[NC*4*32];
    __shared__ float sK[QD*4*32];
    int tid = threadIdx.x;
    int b = blockIdx.x >> 2;
    int w0 = (blockIdx.x & 3) * 32;
    int w = tid & 31, ch = tid >> 5;

    float acc[16];
#pragma unroll
    for (int i = 0; i < 16; i++) acc[i] = 0.f;

    const float* Vb = g_V + (size_t)b*NC*HWSZ + w0;
    const float* Kb = g_K + (size_t)b*QD*HWSZ + w0;

    for (int h0 = 0; h0 < NH; h0 += 4) {
        __syncthreads();
#pragma unroll
        for (int i = 0; i < 2; i++) {
            int idx4 = tid + i*1024;
            int c = idx4 >> 5, rem = idx4 & 31;
            int hh = rem >> 3, j = rem & 7;
            float4 v = *reinterpret_cast<const float4*>(
                Vb + (size_t)c*HWSZ + (h0 + hh)*NW + j*4);
            *reinterpret_cast<float4*>(&sV[(c*4 + hh)*32 + j*4]) = v;
        }
        if (tid < 256) {
            int q = tid >> 5, rem = tid & 31;
            int hh = rem >> 3, j = rem & 7;
            float4 v = *reinterpret_cast<const float4*>(
                Kb + (size_t)q*HWSZ + (h0 + hh)*NW + j*4);
            *reinterpret_cast<float4*>(&sK[(q*4 + hh)*32 + j*4]) = v;
        }
        __syncthreads();
#pragma unroll
        for (int hh = 0; hh < 4; hh++) {
            float v0 = sV[(ch*4 + hh)*32 + w];
            float v1 = sV[((ch + 32)*4 + hh)*32 + w];
#pragma unroll
            for (int q = 0; q < QD; q++) {
                float kk = sK[(q*4 + hh)*32 + w];
                acc[q]     = fmaf(v0, kk, acc[q]);
                acc[8 + q] = fmaf(v1, kk, acc[8 + q]);
            }
        }
    }
    float* out = g_MH + (size_t)b*NC*QD*NW + w0 + w;
#pragma unroll
    for (int q = 0; q < QD; q++) {
        out[(size_t)(ch*QD + q)*NW]        = acc[q];
        out[(size_t)((ch + 32)*QD + q)*NW] = acc[8 + q];
    }
}

// ---------------------------------------------------------------
// Kernel D: out = gamma*( sum_q Q*(MH+MW) + NEG*V ) + x
// ---------------------------------------------------------------
__global__ void __launch_bounds__(256, 6) kout(
    const float* __restrict__ x,
    const float* __restrict__ gamma,
    float* __restrict__ out)
{
    __shared__ __align__(16) float sMH[16*QD*32];
    __shared__ __align__(16) float sMW[8*16*QD];
    int tid = threadIdx.x;
    int w0 = blockIdx.x * 32, h0 = blockIdx.y * 8;
    int b  = blockIdx.z >> 2;
    int c0 = (blockIdx.z & 3) * 16;
    int lane = tid & 31, hl = tid >> 5;

#pragma unroll
    for (int i = 0; i < 4; i++) {
        int idx4 = tid + i*256;
        int cql = idx4 >> 3, j = idx4 & 7;
        float4 v = *reinterpret_cast<const float4*>(
            g_MH + ((size_t)b*NC*QD + c0*QD + cql)*NW + w0 + j*4);
        *reinterpret_cast<float4*>(&sMH[cql*32 + j*4]) = v;
    }
    {
        int hh = tid >> 5, j = tid & 31;
        float4 v = *reinterpret_cast<const float4*>(
            g_MW + ((size_t)(b*NH + h0 + hh)*NC + c0)*QD + j*4);
        *reinterpret_cast<float4*>(&sMW[hh*(16*QD) + j*4]) = v;
    }

    int h = h0 + hl, w = w0 + lane;
    float Qr[QD];
#pragma unroll
    for (int q = 0; q < QD; q++)
        Qr[q] = g_Q[((size_t)b*QD + q)*HWSZ + h*NW + w];
    float gm = gamma[0];
    __syncthreads();

    const float* Vp = g_V + ((size_t)b*NC + c0)*HWSZ + h*NW + w;
    const float* Xp = x   + ((size_t)b*NC + c0)*HWSZ + h*NW + w;
    float*       Op = out + ((size_t)b*NC + c0)*HWSZ + h*NW + w;

#pragma unroll
    for (int cc = 0; cc < 16; cc += 4) {
        float v[4], xr[4];
#pragma unroll
        for (int u = 0; u < 4; u++) {
            v[u]  = Vp[(size_t)(cc+u)*HWSZ];
            xr[u] = Xp[(size_t)(cc+u)*HWSZ];
        }
#pragma unroll
        for (int u = 0; u < 4; u++) {
            int c = cc + u;
            const float* mh = &sMH[c*QD*32 + lane];
            const float4* mwp = reinterpret_cast<const float4*>(&sMW[hl*(16*QD) + c*QD]);
            float4 a = mwp[0], bb = mwp[1];
            float acc;
            acc  = (mh[0]   + a.x)  * Qr[0];
            acc += (mh[32]  + a.y)  * Qr[1];
            acc += (mh[64]  + a.z)  * Qr[2];
            acc += (mh[96]  + a.w)  * Qr[3];
            acc += (mh[128] + bb.x) * Qr[4];
            acc += (mh[160] + bb.y) * Qr[5];
            acc += (mh[192] + bb.z) * Qr[6];
            acc += (mh[224] + bb.w) * Qr[7];
            Op[(size_t)c*HWSZ] = fmaf(gm, fmaf(NEGV, v[u], acc), xr[u]);
        }
    }
}

// ---------------------------------------------------------------
extern "C" void kernel_launch(void* const* d_in, const int* in_sizes, int n_in,
                              void* d_out, int out_size)
{
    const float* x     = (const float*)d_in[0];
    const float* wq    = (const float*)d_in[1];
    const float* bq    = (const float*)d_in[2];
    const float* wk    = (const float*)d_in[3];
    const float* bk    = (const float*)d_in[4];
    const float* wv    = (const float*)d_in[5];
    const float* bv    = (const float*)d_in[6];
    const float* gamma = (const float*)d_in[7];
    float* out = (float*)d_out;

    const int smproj = SM_TOT * sizeof(float);   // ~58 KB
    cudaFuncSetAttribute(kproj, cudaFuncAttributeMaxDynamicSharedMemorySize,
                         smproj);

    wsplit<<<10, 256>>>(wq, bq, wk, bk, wv, bv);
    kproj<<<NB*NH, 256, smproj>>>(x);
    kmh<<<NB*4, 1024>>>();
    kout<<<dim3(NW/32, NH/8, NB*4), 256>>>(x, gamma, out);
}

// round 14
// speedup vs baseline: 1.2056x; 1.0561x over previous
#include <cuda_runtime.h>
#include <math.h>
#include <stdint.h>

#define NB 32
#define NC 64
#define NH 128
#define NW 128
#define QD 8
#define HWSZ (NH*NW)
#define NEGV (-1e4f)

// ---- device scratch ----
__device__ float g_Q[(size_t)NB*QD*HWSZ];     // [b][q][h][w]
__device__ float g_K[(size_t)NB*QD*HWSZ];     // [b][q][h][w]
__device__ float g_V[(size_t)NB*NC*HWSZ];     // [b][c][h][w]
__device__ float g_MH[(size_t)NB*NC*QD*NW];   // [b][c*8+q][w]  h-half 0
__device__ float g_MH2[(size_t)NB*NC*QD*NW];  // [b][c*8+q][w]  h-half 1
__device__ float g_MW[(size_t)NB*NH*NC*QD];   // [b][h][c*8+q]
__device__ uint32_t g_Whi[80*32];             // pre-split W hi (bf16x2 pairs)
__device__ uint32_t g_Wlo[80*32];             // pre-split W lo
__device__ float    g_Bia[80];                // fused bias

__device__ __forceinline__ float softplusf(float v) {
    return fmaxf(v, 0.f) + log1pf(expf(-fabsf(v)));
}

// pack two f32 -> bf16x2 reg: result = {h1 = bf16(hi_src), h0 = bf16(lo_src)}
__device__ __forceinline__ uint32_t packbf(float h1src, float h0src) {
    uint32_t d;
    asm("cvt.rn.bf16x2.f32 %0, %1, %2;" : "=r"(d) : "f"(h1src), "f"(h0src));
    return d;
}
__device__ __forceinline__ float bf_lo(uint32_t p) {   // value of h0
    return __uint_as_float(p << 16);
}
__device__ __forceinline__ float bf_hi(uint32_t p) {   // value of h1
    return __uint_as_float(p & 0xFFFF0000u);
}

// warp-level bf16 mma m16n8k16 (base ISA, sm_80+)
#define MMA_BF16(c, a, bb)                                                    \
    asm volatile("mma.sync.aligned.m16n8k16.row.col.f32.bf16.bf16.f32 "       \
        "{%0,%1,%2,%3}, {%4,%5,%6,%7}, {%8,%9}, {%0,%1,%2,%3};"               \
        : "+f"((c)[0]), "+f"((c)[1]), "+f"((c)[2]), "+f"((c)[3])              \
        : "r"((a)[0]), "r"((a)[1]), "r"((a)[2]), "r"((a)[3]),                 \
          "r"((bb)[0]), "r"((bb)[1]))

// ---- kproj smem layout (u32 words), PT = 128 px = one (b,h) row ----
#define PT    128
#define WSTR  36               // W: [o][36]  (bank = 4*lq+lr, distinct)
#define XP    136              // X: [cp][136] (bank = 8*lr+lq, distinct)
#define SM_WHI 0                                   // 80*36 = 2880
#define SM_WLO (SM_WHI + 80*WSTR)                  // 2880
#define SM_XHI (SM_WLO + 80*WSTR)                  // 5760
#define SM_XLO (SM_XHI + 32*XP)                    // 10112
#define SM_BIA (SM_XLO + 32*XP)                    // 14464
#define SM_TOT (SM_BIA + 80)                       // 14544 words = 58176 B
// post-mainloop reuse: sVf = [0..64*132), sKf = [64*132..72*132)

// ---------------------------------------------------------------
// Kernel W: one-time weight split (hi/lo bf16x2) + bias gather.
// ---------------------------------------------------------------
__global__ void wsplit(
    const float* __restrict__ wq, const float* __restrict__ bq,
    const float* __restrict__ wk, const float* __restrict__ bk,
    const float* __restrict__ wv, const float* __restrict__ bv)
{
    int i = blockIdx.x * 256 + threadIdx.x;
    if (i < 80*32) {
        int o = i >> 5, cp = i & 31;
        const float* wrow = (o < 64) ? (wv + o*64)
                          : (o < 72) ? (wq + (o-64)*64)
                          :            (wk + (o-72)*64);
        float2 wp = *reinterpret_cast<const float2*>(wrow + 2*cp);
        uint32_t hi = packbf(wp.y, wp.x);
        uint32_t lo = packbf(wp.y - bf_hi(hi), wp.x - bf_lo(hi));
        g_Whi[i] = hi;
        g_Wlo[i] = lo;
    }
    if (i < 80)
        g_Bia[i] = (i < 64) ? bv[i] : (i < 72) ? bq[i-64] : bk[i-72];
}

// ---------------------------------------------------------------
// Kernel A: 1x1 projections via mma.sync bf16 m16n8k16 (3-way split)
// FUSED with the M_W row reduction. Block = one (b,h) row, 8 warps.
// ---------------------------------------------------------------
__global__ void __launch_bounds__(256, 3) kproj(const float* __restrict__ x)
{
    extern __shared__ float smf[];
    uint32_t* sm = reinterpret_cast<uint32_t*>(smf);
    int tid = threadIdx.x;
    int b  = blockIdx.x >> 7;
    int h  = blockIdx.x & 127;
    int p0 = h * PT;

    // ---- stage X hi/lo FIRST (DRAM latency starts now) ----
    {
        const float* xb = x + (size_t)b*NC*HWSZ + p0;
        for (int i = tid; i < 32*32; i += 256) {      // 32 cp * 32 px-quads
            int cp = i >> 5, p4 = i & 31;
            const float* x0 = xb + (size_t)(2*cp)*HWSZ + p4*4;
            float4 A4 = *reinterpret_cast<const float4*>(x0);         // c=2cp
            float4 B4 = *reinterpret_cast<const float4*>(x0 + HWSZ);  // c=2cp+1
            float av[4] = {A4.x, A4.y, A4.z, A4.w};
            float bv4[4] = {B4.x, B4.y, B4.z, B4.w};
            uint32_t hi[4], lo[4];
#pragma unroll
            for (int u = 0; u < 4; u++) {
                hi[u] = packbf(bv4[u], av[u]);
                lo[u] = packbf(bv4[u] - bf_hi(hi[u]), av[u] - bf_lo(hi[u]));
            }
            *reinterpret_cast<uint4*>(&sm[SM_XHI + cp*XP + p4*4]) =
                make_uint4(hi[0], hi[1], hi[2], hi[3]);
            *reinterpret_cast<uint4*>(&sm[SM_XLO + cp*XP + p4*4]) =
                make_uint4(lo[0], lo[1], lo[2], lo[3]);
        }
    }
    // ---- W: plain copy of the pre-split weights (L2-hot) ----
    for (int i = tid; i < 80*32; i += 256) {
        int o = i >> 5, cp = i & 31;
        sm[SM_WHI + o*WSTR + cp] = g_Whi[i];
        sm[SM_WLO + o*WSTR + cp] = g_Wlo[i];
    }
    if (tid < 80) smf[SM_BIA + tid] = g_Bia[tid];
    __syncthreads();

    int lane = tid & 31, wid = tid >> 5;
    int lq = lane >> 2;           // 0..7
    int lr = lane & 3;            // 0..3
    int wpx = wid * 16;           // warp pixel base (8 warps x 16 px)

    float acc[5][2][4];
#pragma unroll
    for (int mt = 0; mt < 5; mt++) {
        float b0 = smf[SM_BIA + mt*16 + lq];
        float b1 = smf[SM_BIA + mt*16 + 8 + lq];
#pragma unroll
        for (int j = 0; j < 2; j++) {
            acc[mt][j][0] = b0; acc[mt][j][1] = b0;
            acc[mt][j][2] = b1; acc[mt][j][3] = b1;
        }
    }

#pragma unroll
    for (int ks = 0; ks < 4; ks++) {      // K = 4 x 16
        uint32_t bh[2][2], bl[2][2];
#pragma unroll
        for (int j = 0; j < 2; j++) {
            int r0 = (ks*8 + lr)*XP + wpx + j*8 + lq;
            bh[j][0] = sm[SM_XHI + r0]; bh[j][1] = sm[SM_XHI + r0 + 4*XP];
            bl[j][0] = sm[SM_XLO + r0]; bl[j][1] = sm[SM_XLO + r0 + 4*XP];
        }
        uint32_t ah[5][4];
#pragma unroll
        for (int mt = 0; mt < 5; mt++) {
            int r0 = (mt*16 + lq)*WSTR + ks*8 + lr;
            int r1 = r0 + 8*WSTR;
            ah[mt][0] = sm[SM_WHI + r0];     ah[mt][1] = sm[SM_WHI + r1];
            ah[mt][2] = sm[SM_WHI + r0 + 4]; ah[mt][3] = sm[SM_WHI + r1 + 4];
        }
#pragma unroll
        for (int mt = 0; mt < 5; mt++)
#pragma unroll
            for (int j = 0; j < 2; j++) MMA_BF16(acc[mt][j], ah[mt], bh[j]);
#pragma unroll
        for (int mt = 0; mt < 5; mt++)
#pragma unroll
            for (int j = 0; j < 2; j++) MMA_BF16(acc[mt][j], ah[mt], bl[j]);
        // load al LATE so it is not co-live with ah across passes 1-2
        uint32_t al[5][4];
#pragma unroll
        for (int mt = 0; mt < 5; mt++) {
            int r0 = (mt*16 + lq)*WSTR + ks*8 + lr;
            int r1 = r0 + 8*WSTR;
            al[mt][0] = sm[SM_WLO + r0];     al[mt][1] = sm[SM_WLO + r1];
            al[mt][2] = sm[SM_WLO + r0 + 4]; al[mt][3] = sm[SM_WLO + r1 + 4];
        }
#pragma unroll
        for (int mt = 0; mt < 5; mt++)
#pragma unroll
            for (int j = 0; j < 2; j++) MMA_BF16(acc[mt][j], al[mt], bh[j]);
    }

    // ---- epilogue: store V/Q/K to global AND V,K (f32) to smem ----
    __syncthreads();               // mainloop smem reads done before overwrite
    float* sVf = smf;              // [64][132]
    float* sKf = smf + 64*132;     // [8][132]
    float* Vb = g_V + (size_t)b*NC*HWSZ + p0;
#pragma unroll
    for (int mt = 0; mt < 4; mt++) {
        int r0 = mt*16 + lq, r1 = r0 + 8;
#pragma unroll
        for (int j = 0; j < 2; j++) {
            int px = wpx + j*8 + lr*2;
            float2 v0 = make_float2(acc[mt][j][0], acc[mt][j][1]);
            float2 v1 = make_float2(acc[mt][j][2], acc[mt][j][3]);
            *reinterpret_cast<float2*>(Vb + (size_t)r0*HWSZ + px) = v0;
            *reinterpret_cast<float2*>(Vb + (size_t)r1*HWSZ + px) = v1;
            *reinterpret_cast<float2*>(&sVf[r0*132 + px]) = v0;
            *reinterpret_cast<float2*>(&sVf[r1*132 + px]) = v1;
        }
    }
    {
        float* Qb = g_Q + ((size_t)b*QD + lq)*HWSZ + p0;
        float* Kb = g_K + ((size_t)b*QD + lq)*HWSZ + p0;
#pragma unroll
        for (int j = 0; j < 2; j++) {
            int px = wpx + j*8 + lr*2;
            float2 qv = make_float2(softplusf(acc[4][j][0]),
                                    softplusf(acc[4][j][1]));
            float2 kv = make_float2(softplusf(acc[4][j][2]),
                                    softplusf(acc[4][j][3]));
            *reinterpret_cast<float2*>(Qb + px) = qv;
            *reinterpret_cast<float2*>(Kb + px) = kv;
            *reinterpret_cast<float2*>(&sKf[lq*132 + px]) = kv;
        }
    }
    __syncthreads();

    // ---- fused M_W: M_W[b,h,c,q] = sum_w V[c,w]*K[q,w] ----
    {
        int c = tid >> 2, q0 = (tid & 3) * 2;
        float a0 = 0.f, a1 = 0.f;
#pragma unroll 8
        for (int w4 = 0; w4 < NW/4; w4++) {
            float4 v  = *reinterpret_cast<const float4*>(&sVf[c*132 + w4*4]);
            float4 k0 = *reinterpret_cast<const float4*>(&sKf[q0*132 + w4*4]);
            float4 k1 = *reinterpret_cast<const float4*>(&sKf[(q0+1)*132 + w4*4]);
            a0 = fmaf(v.x, k0.x, a0); a0 = fmaf(v.y, k0.y, a0);
            a0 = fmaf(v.z, k0.z, a0); a0 = fmaf(v.w, k0.w, a0);
            a1 = fmaf(v.x, k1.x, a1); a1 = fmaf(v.y, k1.y, a1);
            a1 = fmaf(v.z, k1.z, a1); a1 = fmaf(v.w, k1.w, a1);
        }
        float2* mwout = reinterpret_cast<float2*>(
            g_MW + ((size_t)b*NH + h)*NC*QD);
        mwout[tid] = make_float2(a0, a1);
    }
}

// ---------------------------------------------------------------
// Kernel C: partial M_H over an h-half, software-pipelined.
// grid = NB*4wt*2half; block 1024. Prefetch chunk i+1 regs during
// compute of chunk i so DRAM latency overlaps FMA.
// ---------------------------------------------------------------
__global__ void __launch_bounds__(1024) kmh()
{
    __shared__ float sV[NC*4*32];
    __shared__ float sK[QD*4*32];
    int tid = threadIdx.x;
    int blk = blockIdx.x;
    int half = blk & 1;
    int w0 = ((blk >> 1) & 3) * 32;
    int b = blk >> 3;
    int w = tid & 31, ch = tid >> 5;

    float acc[16];
#pragma unroll
    for (int i = 0; i < 16; i++) acc[i] = 0.f;

    const float* Vb = g_V + (size_t)b*NC*HWSZ + w0;
    const float* Kb = g_K + (size_t)b*QD*HWSZ + w0;
    int hbeg = half * (NH/2);

    // staging index decomposition (fixed per thread)
    int vc0  = tid >> 5,            vrem0 = tid & 31;
    int vhh0 = vrem0 >> 3,          vj0   = vrem0 & 7;
    int vc1  = (tid + 1024) >> 5,   vrem1 = (tid + 1024) & 31;
    int vhh1 = vrem1 >> 3,          vj1   = vrem1 & 7;
    int kq   = tid >> 5,            krem  = tid & 31;
    int khh  = krem >> 3,           kj    = krem & 7;

    // prefetch chunk 0
    float4 pv0, pv1, pk;
    {
        int h0 = hbeg;
        pv0 = *reinterpret_cast<const float4*>(
            Vb + (size_t)vc0*HWSZ + (h0 + vhh0)*NW + vj0*4);
        pv1 = *reinterpret_cast<const float4*>(
            Vb + (size_t)vc1*HWSZ + (h0 + vhh1)*NW + vj1*4);
        if (tid < 256)
            pk = *reinterpret_cast<const float4*>(
                Kb + (size_t)kq*HWSZ + (h0 + khh)*NW + kj*4);
    }

    for (int ci = 0; ci < 16; ci++) {
        __syncthreads();   // previous compute done; smem free
        *reinterpret_cast<float4*>(&sV[(vc0*4 + vhh0)*32 + vj0*4]) = pv0;
        *reinterpret_cast<float4*>(&sV[(vc1*4 + vhh1)*32 + vj1*4]) = pv1;
        if (tid < 256)
            *reinterpret_cast<float4*>(&sK[(kq*4 + khh)*32 + kj*4]) = pk;
        // prefetch next chunk (latency overlaps the compute below)
        if (ci < 15) {
            int h1 = hbeg + (ci + 1)*4;
            pv0 = *reinterpret_cast<const float4*>(
                Vb + (size_t)vc0*HWSZ + (h1 + vhh0)*NW + vj0*4);
            pv1 = *reinterpret_cast<const float4*>(
                Vb + (size_t)vc1*HWSZ + (h1 + vhh1)*NW + vj1*4);
            if (tid < 256)
                pk = *reinterpret_cast<const float4*>(
                    Kb + (size_t)kq*HWSZ + (h1 + khh)*NW + kj*4);
        }
        __syncthreads();   // smem ready
#pragma unroll
        for (int hh = 0; hh < 4; hh++) {
            float v0 = sV[(ch*4 + hh)*32 + w];
            float v1 = sV[((ch + 32)*4 + hh)*32 + w];
#pragma unroll
            for (int q = 0; q < QD; q++) {
                float kk = sK[(q*4 + hh)*32 + w];
                acc[q]     = fmaf(v0, kk, acc[q]);
                acc[8 + q] = fmaf(v1, kk, acc[8 + q]);
            }
        }
    }
    float* out = (half ? g_MH2 : g_MH) + (size_t)b*NC*QD*NW + w0 + w;
#pragma unroll
    for (int q = 0; q < QD; q++) {
        out[(size_t)(ch*QD + q)*NW]        = acc[q];
        out[(size_t)((ch + 32)*QD + q)*NW] = acc[8 + q];
    }
}

// ---------------------------------------------------------------
// Kernel D: out = gamma*( sum_q Q*(MH0+MH1+MW) + NEG*V ) + x
// ---------------------------------------------------------------
__global__ void __launch_bounds__(256, 6) kout(
    const float* __restrict__ x,
    const float* __restrict__ gamma,
    float* __restrict__ out)
{
    __shared__ __align__(16) float sMH[16*QD*32];
    __shared__ __align__(16) float sMW[8*16*QD];
    int tid = threadIdx.x;
    int w0 = blockIdx.x * 32, h0 = blockIdx.y * 8;
    int b  = blockIdx.z >> 2;
    int c0 = (blockIdx.z & 3) * 16;
    int lane = tid & 31, hl = tid >> 5;

#pragma unroll
    for (int i = 0; i < 4; i++) {
        int idx4 = tid + i*256;
        int cql = idx4 >> 3, j = idx4 & 7;
        size_t off = ((size_t)b*NC*QD + c0*QD + cql)*NW + w0 + j*4;
        float4 v  = *reinterpret_cast<const float4*>(g_MH  + off);
        float4 v2 = *reinterpret_cast<const float4*>(g_MH2 + off);
        v.x += v2.x; v.y += v2.y; v.z += v2.z; v.w += v2.w;
        *reinterpret_cast<float4*>(&sMH[cql*32 + j*4]) = v;
    }
    {
        int hh = tid >> 5, j = tid & 31;
        float4 v = *reinterpret_cast<const float4*>(
            g_MW + ((size_t)(b*NH + h0 + hh)*NC + c0)*QD + j*4);
        *reinterpret_cast<float4*>(&sMW[hh*(16*QD) + j*4]) = v;
    }

    int h = h0 + hl, w = w0 + lane;
    float Qr[QD];
#pragma unroll
    for (int q = 0; q < QD; q++)
        Qr[q] = g_Q[((size_t)b*QD + q)*HWSZ + h*NW + w];
    float gm = gamma[0];
    __syncthreads();

    const float* Vp = g_V + ((size_t)b*NC + c0)*HWSZ + h*NW + w;
    const float* Xp = x   + ((size_t)b*NC + c0)*HWSZ + h*NW + w;
    float*       Op = out + ((size_t)b*NC + c0)*HWSZ + h*NW + w;

#pragma unroll
    for (int cc = 0; cc < 16; cc += 4) {
        float v[4], xr[4];
#pragma unroll
        for (int u = 0; u < 4; u++) {
            v[u]  = Vp[(size_t)(cc+u)*HWSZ];
            xr[u] = Xp[(size_t)(cc+u)*HWSZ];
        }
#pragma unroll
        for (int u = 0; u < 4; u++) {
            int c = cc + u;
            const float* mh = &sMH[c*QD*32 + lane];
            const float4* mwp = reinterpret_cast<const float4*>(&sMW[hl*(16*QD) + c*QD]);
            float4 a = mwp[0], bb = mwp[1];
            float acc;
            acc  = (mh[0]   + a.x)  * Qr[0];
            acc += (mh[32]  + a.y)  * Qr[1];
            acc += (mh[64]  + a.z)  * Qr[2];
            acc += (mh[96]  + a.w)  * Qr[3];
            acc += (mh[128] + bb.x) * Qr[4];
            acc += (mh[160] + bb.y) * Qr[5];
            acc += (mh[192] + bb.z) * Qr[6];
            acc += (mh[224] + bb.w) * Qr[7];
            Op[(size_t)c*HWSZ] = fmaf(gm, fmaf(NEGV, v[u], acc), xr[u]);
        }
    }
}

// ---------------------------------------------------------------
extern "C" void kernel_launch(void* const* d_in, const int* in_sizes, int n_in,
                              void* d_out, int out_size)
{
    const float* x     = (const float*)d_in[0];
    const float* wq    = (const float*)d_in[1];
    const float* bq    = (const float*)d_in[2];
    const float* wk    = (const float*)d_in[3];
    const float* bk    = (const float*)d_in[4];
    const float* wv    = (const float*)d_in[5];
    const float* bv    = (const float*)d_in[6];
    const float* gamma = (const float*)d_in[7];
    float* out = (float*)d_out;

    const int smproj = SM_TOT * sizeof(float);   // ~58 KB
    cudaFuncSetAttribute(kproj, cudaFuncAttributeMaxDynamicSharedMemorySize,
                         smproj);

    wsplit<<<10, 256>>>(wq, bq, wk, bk, wv, bv);
    kproj<<<NB*NH, 256, smproj>>>(x);
    kmh<<<NB*8, 1024>>>();
    kout<<<dim3(NW/32, NH/8, NB*4), 256>>>(x, gamma, out);
}